// round 15
// baseline (speedup 1.0000x reference)
#include <cuda_runtime.h>

#define FS 4096
#define FT 4096
#define NV 2048
#define NPTS (FS * 8)            // 32768 sample points
#define NPE  (NPTS + FS)         // + 4096 src barycenters = 36864
#define TPB 256
#define RTPB 256
#define PT 4                     // points per thread (tgt path only)
#define SLICES 8
#define SL 512                   // candidates per slice
#define CH 8                     // chunk size
#define NCH (SL / CH)            // 64 chunks per slice
#define SRC_PG (NPTS / (RTPB * 2))    // 64 point-groups (512 pts each)
#define TGT_PG (NPE  / (RTPB * PT))   // 36 point-groups (1024 pts each)
#define SRC_BLKS (SRC_PG * SLICES)    // 512
#define TGT_BLKS (TGT_PG * SLICES)    // 288
#define MRG_TPB 128
#define MRG_BLK (NPTS / MRG_TPB)      // 256
#define FSUM_BLK (FS / MRG_TPB)       // 32
#define PART_BLK (MRG_BLK + FSUM_BLK) // 288

typedef unsigned long long u64;

// Scratch (allocation-free: __device__ globals)
__device__ float4 g_src_bc[FS];        // xyz, w = 0.5*|bc|^2 (candidate form)
__device__ float4 g_tgt_bc[FT];        // xyz, w = 0.5*|bc|^2
__device__ float4 g_pts[NPE];          // xyz, w = |p|^2 (full norm)
// packed per-slice record: top-6 chunk-min values + global chunk ids (bitcast)
__device__ float4 g_list[SLICES][NPTS][3];
__device__ unsigned g_mtei[NPE];       // order-preserving float keys, atomicMin
__device__ float  g_partial[PART_BLK];
__device__ unsigned g_mcount;          // zero-initialized; self-resetting

// ---- packed f32x2 helpers (sm_103a) ---------------------------------------
__device__ __forceinline__ u64 pk2(float a, float b) {
    u64 r; asm("mov.b64 %0,{%1,%2};" : "=l"(r) : "f"(a), "f"(b)); return r;
}
__device__ __forceinline__ u64 fma2(u64 a, u64 b, u64 c) {
    u64 d; asm("fma.rn.f32x2 %0,%1,%2,%3;" : "=l"(d) : "l"(a), "l"(b), "l"(c)); return d;
}
__device__ __forceinline__ void upk2(u64 d, float& x, float& y) {
    asm("mov.b64 {%0,%1},%2;" : "=f"(x), "=f"(y) : "l"(d));
}

// order-preserving float <-> uint key (f1 < f2  <=>  key(f1) < key(f2), unsigned)
__device__ __forceinline__ unsigned fkey(float f) {
    unsigned b = __float_as_uint(f);
    return (b & 0x80000000u) ? ~b : (b | 0x80000000u);
}
__device__ __forceinline__ float funkey(unsigned k) {
    return __uint_as_float((k & 0x80000000u) ? (k ^ 0x80000000u) : ~k);
}

// ascending insert, strict < keeps earlier (lower-index) candidate on ties
__device__ __forceinline__ void try_insert(float e, int j, float be[6], int bi[6]) {
    if (e < be[5]) {
        be[5] = e; bi[5] = j;
        #pragma unroll
        for (int k = 5; k > 0; --k) {
            if (be[k] < be[k-1]) {
                float te = be[k]; be[k] = be[k-1]; be[k-1] = te;
                int   ti = bi[k]; bi[k] = bi[k-1]; bi[k-1] = ti;
            }
        }
    }
}

// Pack SL candidates (pair-interleaved) from g[off..off+SL) into smem.
// With RTPB=256 and SL=512 this is exactly one pair per thread.
__device__ __forceinline__ void load_packed_slice(ulonglong2* s, const float4* g,
                                                  int off, int tid) {
    #pragma unroll
    for (int t = tid; t < SL/2; t += RTPB) {
        float4 a = g[off + 2*t], b = g[off + 2*t + 1];
        ulonglong2 u0, u1;
        u0.x = pk2(a.x, b.x); u0.y = pk2(a.y, b.y);
        u1.x = pk2(a.z, b.z); u1.y = pk2(a.w, b.w);
        s[2*t]   = u0;
        s[2*t+1] = u1;
    }
}

// ---------------------------------------------------------------------------
// Kernel 1: barycenters + sampled points (vertex arrays staged in smem).
// Also re-initializes g_mtei each call (graph-replay safe: same stream).
// ---------------------------------------------------------------------------
__global__ void __launch_bounds__(TPB) prep_kernel(
        const float* __restrict__ sv, const int* __restrict__ sf,
        const float* __restrict__ tv, const int* __restrict__ tf,
        const float* __restrict__ r1u, const float* __restrict__ r2u) {
    __shared__ float s_v[NV * 6];      // sv then tv, 48 KB
    int tid = threadIdx.x;
    {
        const float4* sv4 = (const float4*)sv;
        const float4* tv4 = (const float4*)tv;
        float4* s4 = (float4*)s_v;
        #pragma unroll
        for (int k = 0; k < (NV*3)/(4*TPB); k++) {
            int idx = tid + k * TPB;
            s4[idx]              = sv4[idx];
            s4[idx + (NV*3)/4]   = tv4[idx];
        }
    }
    __syncthreads();
    const float* s_sv = s_v;
    const float* s_tv = s_v + NV * 3;

    int i = blockIdx.x * TPB + tid;
    g_mtei[i] = 0xFFFFFFFFu;           // +inf key
    if (i < FS) {
        g_mtei[NPTS + i] = 0xFFFFFFFFu;
        int a = sf[3*i+0], b = sf[3*i+1], c = sf[3*i+2];
        float x = (s_sv[3*a+0] + s_sv[3*b+0] + s_sv[3*c+0]) * (1.0f/3.0f);
        float y = (s_sv[3*a+1] + s_sv[3*b+1] + s_sv[3*c+1]) * (1.0f/3.0f);
        float z = (s_sv[3*a+2] + s_sv[3*b+2] + s_sv[3*c+2]) * (1.0f/3.0f);
        float n2 = x*x + y*y + z*z;
        g_src_bc[i]      = make_float4(x, y, z, 0.5f*n2);
        g_pts[NPTS + i]  = make_float4(x, y, z, n2);
        int ta = tf[i], tb = tf[FT + i], tc = tf[2*FT + i];
        float tx = (s_tv[3*ta+0] + s_tv[3*tb+0] + s_tv[3*tc+0]) * (1.0f/3.0f);
        float ty = (s_tv[3*ta+1] + s_tv[3*tb+1] + s_tv[3*tc+1]) * (1.0f/3.0f);
        float tz = (s_tv[3*ta+2] + s_tv[3*tb+2] + s_tv[3*tc+2]) * (1.0f/3.0f);
        g_tgt_bc[i] = make_float4(tx, ty, tz, 0.5f*(tx*tx + ty*ty + tz*tz));
    }
    {
        int f = i >> 3;
        int a = sf[3*f+0], b = sf[3*f+1], c = sf[3*f+2];
        float r1 = sqrtf(r1u[i]);
        float r2 = r2u[i];
        float w1 = 1.0f - r1;
        float w2 = r1 * (1.0f - r2);
        float w3 = r1 * r2;
        float x = w1*s_sv[3*a+0] + w2*s_sv[3*b+0] + w3*s_sv[3*c+0];
        float y = w1*s_sv[3*a+1] + w2*s_sv[3*b+1] + w3*s_sv[3*c+1];
        float z = w1*s_sv[3*a+2] + w2*s_sv[3*b+2] + w3*s_sv[3*c+2];
        g_pts[i] = make_float4(x, y, z, x*x + y*y + z*z);
    }
}

// ---------------------------------------------------------------------------
// Kernel 2 (fused): src stage-1 chunk-minima top-6 (P=2) + tgt min (P=4,
// atomic-min accumulation across slices). 256 threads/block.
// ---------------------------------------------------------------------------
__global__ void __launch_bounds__(RTPB) rev_kernel() {
    __shared__ ulonglong2 s_pk[SL];   // 8 KB
    int tid = threadIdx.x;
    int b   = blockIdx.x;

    if (b < SRC_BLKS) {
        int pg  = b >> 3;
        int sl  = b & 7;
        int jb  = sl * SL;
        load_packed_slice(s_pk, g_src_bc, jb, tid);
        __syncthreads();

        int i0 = pg * (RTPB * 2) + tid;
        int i1 = i0 + RTPB;
        float4 p0 = g_pts[i0], p1 = g_pts[i1];
        u64 ax = pk2(-p0.x, -p0.x), ay = pk2(-p0.y, -p0.y), az = pk2(-p0.z, -p0.z);
        u64 bx = pk2(-p1.x, -p1.x), by = pk2(-p1.y, -p1.y), bz = pk2(-p1.z, -p1.z);

        // Stage 1: top-6 of chunk minima, ids = GLOBAL chunk id (sl*NCH + c)
        float beA[6], beB[6]; int biA[6], biB[6];
        #pragma unroll
        for (int k = 0; k < 6; k++) {
            beA[k] = 1e30f; biA[k] = -1;
            beB[k] = 1e30f; biB[k] = -1;
        }
        int gc0 = sl * NCH;
        for (int c = 0; c < NCH; c++) {
            float mA = 1e30f, mB = 1e30f;
            int base = CH * c;
            #pragma unroll
            for (int t = 0; t < CH/2; t++) {
                ulonglong2 U = s_pk[base + 2*t], V = s_pk[base + 2*t + 1];
                u64 dA = fma2(ax, U.x, fma2(ay, U.y, fma2(az, V.x, V.y)));
                u64 dB = fma2(bx, U.x, fma2(by, U.y, fma2(bz, V.x, V.y)));
                float e0, e1;
                upk2(dA, e0, e1); mA = fminf(mA, fminf(e0, e1));
                upk2(dB, e0, e1); mB = fminf(mB, fminf(e0, e1));
            }
            try_insert(mA, gc0 + c, beA, biA);
            try_insert(mB, gc0 + c, beB, biB);
        }

        g_list[sl][i0][0] = make_float4(beA[0], beA[1], beA[2], beA[3]);
        g_list[sl][i0][1] = make_float4(beA[4], beA[5],
                                        __int_as_float(biA[0]), __int_as_float(biA[1]));
        g_list[sl][i0][2] = make_float4(__int_as_float(biA[2]), __int_as_float(biA[3]),
                                        __int_as_float(biA[4]), __int_as_float(biA[5]));
        g_list[sl][i1][0] = make_float4(beB[0], beB[1], beB[2], beB[3]);
        g_list[sl][i1][1] = make_float4(beB[4], beB[5],
                                        __int_as_float(biB[0]), __int_as_float(biB[1]));
        g_list[sl][i1][2] = make_float4(__int_as_float(biB[2]), __int_as_float(biB[3]),
                                        __int_as_float(biB[4]), __int_as_float(biB[5]));
    } else {
        // target min, branchless (P=4), accumulated via exact atomic key-min
        b -= SRC_BLKS;
        int pg = b >> 3;
        int sl = b & 7;
        load_packed_slice(s_pk, g_tgt_bc, sl * SL, tid);
        __syncthreads();

        int i0 = pg * (RTPB * PT) + tid;
        u64 px[PT], py[PT], pz[PT];
        #pragma unroll
        for (int p = 0; p < PT; p++) {
            float4 q = g_pts[i0 + p * RTPB];
            px[p] = pk2(-q.x, -q.x); py[p] = pk2(-q.y, -q.y); pz[p] = pk2(-q.z, -q.z);
        }

        float m0[PT], m1[PT];
        #pragma unroll
        for (int p = 0; p < PT; p++) { m0[p] = 1e30f; m1[p] = 1e30f; }
        #pragma unroll 4
        for (int t = 0; t < SL/2; t++) {
            ulonglong2 U = s_pk[2*t], V = s_pk[2*t+1];
            #pragma unroll
            for (int p = 0; p < PT; p++) {
                u64 d = fma2(px[p], U.x, fma2(py[p], U.y, fma2(pz[p], V.x, V.y)));
                float e0, e1; upk2(d, e0, e1);
                m0[p] = fminf(m0[p], e0);
                m1[p] = fminf(m1[p], e1);
            }
        }
        #pragma unroll
        for (int p = 0; p < PT; p++)
            atomicMin(&g_mtei[i0 + p * RTPB], fkey(fminf(m0[p], m1[p])));
    }
}

// ---------------------------------------------------------------------------
// Kernel 3 (fused): global stage-2 + per-point value (blocks 0..255),
// forward loss (blocks 256..287), last block does final reduction.
// ---------------------------------------------------------------------------
__device__ __forceinline__ void merge6(const float* ea, const int* ia,
                                       const float* eb, const int* ib,
                                       float* eo, int* io) {
    int a = 0, b = 0;
    #pragma unroll
    for (int k = 0; k < 6; k++) {
        float va = ea[a], vb = eb[b];
        bool tA = (va <= vb);          // left = earlier slice = lower chunk ids
        eo[k] = tA ? va : vb;
        io[k] = tA ? ia[a] : ib[b];
        a += tA ? 1 : 0;
        b += tA ? 0 : 1;
    }
}

__device__ __forceinline__ void load_list(int s, int i, float* e, int* id) {
    float4 r0 = g_list[s][i][0];
    float4 r1 = g_list[s][i][1];
    float4 r2 = g_list[s][i][2];
    e[0] = r0.x; e[1] = r0.y; e[2] = r0.z; e[3] = r0.w;
    e[4] = r1.x; e[5] = r1.y;
    id[0] = __float_as_int(r1.z); id[1] = __float_as_int(r1.w);
    id[2] = __float_as_int(r2.x); id[3] = __float_as_int(r2.y);
    id[4] = __float_as_int(r2.z); id[5] = __float_as_int(r2.w);
}

__global__ void __launch_bounds__(MRG_TPB) merge_kernel(
        const float* __restrict__ probs, float* __restrict__ out) {
    int tid = threadIdx.x;
    float val;

    if (blockIdx.x < MRG_BLK) {
        int i     = blockIdx.x * MRG_TPB + tid;
        int sface = i >> 3;

        // global top-6 chunk minima across 8 slices
        float me[6]; int mc[6];
        load_list(0, i, me, mc);
        #pragma unroll
        for (int s = 1; s < SLICES; s++) {
            float eb[6], tmp[6]; int ib[6], tmpi[6];
            load_list(s, i, eb, ib);
            merge6(me, mc, eb, ib, tmp, tmpi);
            #pragma unroll
            for (int k = 0; k < 6; k++) { me[k] = tmp[k]; mc[k] = tmpi[k]; }
        }
        // sort selected chunk ids ascending for stable tie-break on rescan
        #pragma unroll
        for (int a = 1; a < 6; a++)
            #pragma unroll
            for (int b2 = a; b2 > 0; b2--)
                if (mc[b2] < mc[b2-1]) { int t = mc[b2]; mc[b2] = mc[b2-1]; mc[b2-1] = t; }

        // global stage-2: rescan the 6 selected chunks (48 candidates)
        float4 p = g_pts[i];
        float pw = p.w;
        float be[6]; int bi[6];
        #pragma unroll
        for (int k = 0; k < 6; k++) { be[k] = 1e30f; bi[k] = -1; }
        #pragma unroll
        for (int k = 0; k < 6; k++) {
            int j0 = mc[k] * CH;
            #pragma unroll
            for (int t = 0; t < CH; t++) {
                float4 q = g_src_bc[j0 + t];
                float e = fmaf(-p.x, q.x, fmaf(-p.y, q.y, fmaf(-p.z, q.z, q.w)));
                try_insert(e, j0 + t, be, bi);
            }
        }

        int selfpos = 6;
        #pragma unroll
        for (int k = 0; k < 6; k++) if (bi[k] == sface) selfpos = k;
        float s5 = 0.0f;
        #pragma unroll
        for (int k = 0; k < 6; k++) {
            bool inc = (k != selfpos) && (k < 5 || selfpos <= 5);
            if (inc) {
                float d = fmaxf(fmaf(2.0f, be[k], pw), 0.0f);
                s5 += probs[bi[k]] * d;
            }
        }
        float mte  = funkey(g_mtei[i]);
        float pp   = probs[sface];
        float mind = fmaxf(fmaf(2.0f, mte, pw), 0.0f);
        val = fmaf(pp, mind, (1.0f - pp) * (s5 * 0.2f));
    } else {
        // forward loss: one face per thread
        int f = (blockIdx.x - MRG_BLK) * MRG_TPB + tid;
        int i = NPTS + f;
        float mte = funkey(g_mtei[i]);
        float d = fmaxf(fmaf(2.0f, mte, g_pts[i].w), 0.0f);
        val = probs[f] * d;
    }

    __shared__ float red[MRG_TPB];
    red[tid] = val;
    __syncthreads();
    #pragma unroll
    for (int s = MRG_TPB/2; s > 0; s >>= 1) {
        if (tid < s) red[tid] += red[tid + s];
        __syncthreads();
    }

    // last-block final reduction (deterministic: one block, fixed order)
    __shared__ bool s_last;
    if (tid == 0) {
        g_partial[blockIdx.x] = red[0];
        __threadfence();
        unsigned done = atomicAdd(&g_mcount, 1u);
        s_last = (done == PART_BLK - 1);
    }
    __syncthreads();
    if (s_last) {
        volatile float* gp = (volatile float*)g_partial;
        float v = gp[tid] + gp[tid + MRG_TPB];            // 0..255
        if (tid < PART_BLK - 2*MRG_TPB) v += gp[tid + 2*MRG_TPB];  // 256..287
        red[tid] = v;
        __syncthreads();
        #pragma unroll
        for (int s = MRG_TPB/2; s > 0; s >>= 1) {
            if (tid < s) red[tid] += red[tid + s];
            __syncthreads();
        }
        if (tid == 0) {
            out[0] = red[0];
            g_mcount = 0;     // reset for next graph replay
        }
    }
}

extern "C" void kernel_launch(void* const* d_in, const int* in_sizes, int n_in,
                              void* d_out, int out_size) {
    const float* sv    = (const float*)d_in[0];
    const int*   sf    = (const int*)  d_in[1];
    const float* tv    = (const float*)d_in[2];
    const int*   tf    = (const int*)  d_in[3];
    const float* probs = (const float*)d_in[4];
    const float* r1u   = (const float*)d_in[5];
    const float* r2u   = (const float*)d_in[6];

    prep_kernel <<<NPTS / TPB, TPB>>>(sv, sf, tv, tf, r1u, r2u);
    rev_kernel  <<<SRC_BLKS + TGT_BLKS, RTPB>>>();          // 800 blocks, 256 thr
    merge_kernel<<<PART_BLK, MRG_TPB>>>(probs, (float*)d_out);
}

// round 16
// speedup vs baseline: 1.0018x; 1.0018x over previous
#include <cuda_runtime.h>

#define FS 4096
#define FT 4096
#define NV 2048
#define NPTS (FS * 8)            // 32768 sample points
#define NPE  (NPTS + FS)         // + 4096 src barycenters = 36864
#define TPB 256
#define RTPB 128
#define PT 4                     // points per thread (tgt path only)
#define SLICES 8                 // src slices
#define SL 512                   // src candidates per slice
#define CH 8                     // chunk size
#define NCH (SL / CH)            // 64 chunks per slice
#define TSLICES 4                // tgt slices
#define SLT 1024                 // tgt candidates per slice
#define SRC_PG (NPTS / (RTPB * 2))    // 128 point-groups (256 pts each)
#define TGT_PG (NPE  / (RTPB * PT))   // 72 point-groups (512 pts each)
#define SRC_BLKS (SRC_PG * SLICES)    // 1024
#define TGT_BLKS (TGT_PG * TSLICES)   // 288
#define MRG_TPB 128
#define MRG_BLK (NPTS / MRG_TPB)      // 256
#define FSUM_BLK (FS / MRG_TPB)       // 32
#define PART_BLK (MRG_BLK + FSUM_BLK) // 288

typedef unsigned long long u64;

// Scratch (allocation-free: __device__ globals)
__device__ float4 g_src_bc[FS];        // xyz, w = 0.5*|bc|^2 (candidate form)
__device__ float4 g_tgt_bc[FT];        // xyz, w = 0.5*|bc|^2
__device__ float4 g_pts[NPE];          // xyz, w = |p|^2 (full norm)
// packed per-slice record: top-6 chunk-min values + global chunk ids (bitcast)
__device__ float4 g_list[SLICES][NPTS][3];
__device__ unsigned g_mtei[NPE];       // order-preserving float keys, atomicMin
__device__ float  g_partial[PART_BLK];
__device__ unsigned g_mcount;          // zero-initialized; self-resetting

// ---- packed f32x2 helpers (sm_103a) ---------------------------------------
__device__ __forceinline__ u64 pk2(float a, float b) {
    u64 r; asm("mov.b64 %0,{%1,%2};" : "=l"(r) : "f"(a), "f"(b)); return r;
}
__device__ __forceinline__ u64 fma2(u64 a, u64 b, u64 c) {
    u64 d; asm("fma.rn.f32x2 %0,%1,%2,%3;" : "=l"(d) : "l"(a), "l"(b), "l"(c)); return d;
}
__device__ __forceinline__ void upk2(u64 d, float& x, float& y) {
    asm("mov.b64 {%0,%1},%2;" : "=f"(x), "=f"(y) : "l"(d));
}

// order-preserving float <-> uint key (f1 < f2  <=>  key(f1) < key(f2), unsigned)
__device__ __forceinline__ unsigned fkey(float f) {
    unsigned b = __float_as_uint(f);
    return (b & 0x80000000u) ? ~b : (b | 0x80000000u);
}
__device__ __forceinline__ float funkey(unsigned k) {
    return __uint_as_float((k & 0x80000000u) ? (k ^ 0x80000000u) : ~k);
}

// ascending insert, strict < keeps earlier (lower-index) candidate on ties
__device__ __forceinline__ void try_insert(float e, int j, float be[6], int bi[6]) {
    if (e < be[5]) {
        be[5] = e; bi[5] = j;
        #pragma unroll
        for (int k = 5; k > 0; --k) {
            if (be[k] < be[k-1]) {
                float te = be[k]; be[k] = be[k-1]; be[k-1] = te;
                int   ti = bi[k]; bi[k] = bi[k-1]; bi[k-1] = ti;
            }
        }
    }
}

// Pack n candidates (pair-interleaved) from g[off..off+n) into smem.
__device__ __forceinline__ void load_packed_slice(ulonglong2* s, const float4* g,
                                                  int off, int n, int tid) {
    for (int t = tid; t < n/2; t += RTPB) {
        float4 a = g[off + 2*t], b = g[off + 2*t + 1];
        ulonglong2 u0, u1;
        u0.x = pk2(a.x, b.x); u0.y = pk2(a.y, b.y);
        u1.x = pk2(a.z, b.z); u1.y = pk2(a.w, b.w);
        s[2*t]   = u0;
        s[2*t+1] = u1;
    }
}

// ---------------------------------------------------------------------------
// Kernel 1: barycenters + sampled points. Only blocks that compute
// barycenters (i<FS) stage tv; all blocks stage sv.
// ---------------------------------------------------------------------------
__global__ void __launch_bounds__(TPB) prep_kernel(
        const float* __restrict__ sv, const int* __restrict__ sf,
        const float* __restrict__ tv, const int* __restrict__ tf,
        const float* __restrict__ r1u, const float* __restrict__ r2u) {
    __shared__ float s_v[NV * 6];      // sv then (optionally) tv, 48 KB
    int tid = threadIdx.x;
    bool has_fs = (blockIdx.x < FS / TPB);   // first 16 blocks
    {
        const float4* sv4 = (const float4*)sv;
        const float4* tv4 = (const float4*)tv;
        float4* s4 = (float4*)s_v;
        #pragma unroll
        for (int k = 0; k < (NV*3)/(4*TPB); k++) {
            int idx = tid + k * TPB;
            s4[idx] = sv4[idx];
            if (has_fs) s4[idx + (NV*3)/4] = tv4[idx];
        }
    }
    __syncthreads();
    const float* s_sv = s_v;
    const float* s_tv = s_v + NV * 3;

    int i = blockIdx.x * TPB + tid;
    g_mtei[i] = 0xFFFFFFFFu;           // +inf key
    if (i < FS) {
        g_mtei[NPTS + i] = 0xFFFFFFFFu;
        int a = sf[3*i+0], b = sf[3*i+1], c = sf[3*i+2];
        float x = (s_sv[3*a+0] + s_sv[3*b+0] + s_sv[3*c+0]) * (1.0f/3.0f);
        float y = (s_sv[3*a+1] + s_sv[3*b+1] + s_sv[3*c+1]) * (1.0f/3.0f);
        float z = (s_sv[3*a+2] + s_sv[3*b+2] + s_sv[3*c+2]) * (1.0f/3.0f);
        float n2 = x*x + y*y + z*z;
        g_src_bc[i]      = make_float4(x, y, z, 0.5f*n2);
        g_pts[NPTS + i]  = make_float4(x, y, z, n2);
        int ta = tf[i], tb = tf[FT + i], tc = tf[2*FT + i];
        float tx = (s_tv[3*ta+0] + s_tv[3*tb+0] + s_tv[3*tc+0]) * (1.0f/3.0f);
        float ty = (s_tv[3*ta+1] + s_tv[3*tb+1] + s_tv[3*tc+1]) * (1.0f/3.0f);
        float tz = (s_tv[3*ta+2] + s_tv[3*tb+2] + s_tv[3*tc+2]) * (1.0f/3.0f);
        g_tgt_bc[i] = make_float4(tx, ty, tz, 0.5f*(tx*tx + ty*ty + tz*tz));
    }
    {
        int f = i >> 3;
        int a = sf[3*f+0], b = sf[3*f+1], c = sf[3*f+2];
        float r1 = sqrtf(r1u[i]);
        float r2 = r2u[i];
        float w1 = 1.0f - r1;
        float w2 = r1 * (1.0f - r2);
        float w3 = r1 * r2;
        float x = w1*s_sv[3*a+0] + w2*s_sv[3*b+0] + w3*s_sv[3*c+0];
        float y = w1*s_sv[3*a+1] + w2*s_sv[3*b+1] + w3*s_sv[3*c+1];
        float z = w1*s_sv[3*a+2] + w2*s_sv[3*b+2] + w3*s_sv[3*c+2];
        g_pts[i] = make_float4(x, y, z, x*x + y*y + z*z);
    }
}

// ---------------------------------------------------------------------------
// Kernel 2 (fused): src stage-1 chunk-minima top-6 (P=2, 8 slices of 512) +
// tgt min (P=4, 4 slices of 1024, atomic-min accumulation).
// ---------------------------------------------------------------------------
__global__ void __launch_bounds__(RTPB) rev_kernel() {
    __shared__ ulonglong2 s_pk[SLT];   // 16 KB (src uses first 512 entries)
    int tid = threadIdx.x;
    int b   = blockIdx.x;

    if (b < SRC_BLKS) {
        int pg  = b >> 3;
        int sl  = b & 7;
        int jb  = sl * SL;
        load_packed_slice(s_pk, g_src_bc, jb, SL, tid);
        __syncthreads();

        int i0 = pg * 256 + tid;
        int i1 = i0 + 128;
        float4 p0 = g_pts[i0], p1 = g_pts[i1];
        u64 ax = pk2(-p0.x, -p0.x), ay = pk2(-p0.y, -p0.y), az = pk2(-p0.z, -p0.z);
        u64 bx = pk2(-p1.x, -p1.x), by = pk2(-p1.y, -p1.y), bz = pk2(-p1.z, -p1.z);

        // Stage 1: top-6 of chunk minima, ids = GLOBAL chunk id (sl*NCH + c)
        float beA[6], beB[6]; int biA[6], biB[6];
        #pragma unroll
        for (int k = 0; k < 6; k++) {
            beA[k] = 1e30f; biA[k] = -1;
            beB[k] = 1e30f; biB[k] = -1;
        }
        int gc0 = sl * NCH;
        for (int c = 0; c < NCH; c++) {
            float mA = 1e30f, mB = 1e30f;
            int base = CH * c;
            #pragma unroll
            for (int t = 0; t < CH/2; t++) {
                ulonglong2 U = s_pk[base + 2*t], V = s_pk[base + 2*t + 1];
                u64 dA = fma2(ax, U.x, fma2(ay, U.y, fma2(az, V.x, V.y)));
                u64 dB = fma2(bx, U.x, fma2(by, U.y, fma2(bz, V.x, V.y)));
                float e0, e1;
                upk2(dA, e0, e1); mA = fminf(mA, fminf(e0, e1));
                upk2(dB, e0, e1); mB = fminf(mB, fminf(e0, e1));
            }
            try_insert(mA, gc0 + c, beA, biA);
            try_insert(mB, gc0 + c, beB, biB);
        }

        g_list[sl][i0][0] = make_float4(beA[0], beA[1], beA[2], beA[3]);
        g_list[sl][i0][1] = make_float4(beA[4], beA[5],
                                        __int_as_float(biA[0]), __int_as_float(biA[1]));
        g_list[sl][i0][2] = make_float4(__int_as_float(biA[2]), __int_as_float(biA[3]),
                                        __int_as_float(biA[4]), __int_as_float(biA[5]));
        g_list[sl][i1][0] = make_float4(beB[0], beB[1], beB[2], beB[3]);
        g_list[sl][i1][1] = make_float4(beB[4], beB[5],
                                        __int_as_float(biB[0]), __int_as_float(biB[1]));
        g_list[sl][i1][2] = make_float4(__int_as_float(biB[2]), __int_as_float(biB[3]),
                                        __int_as_float(biB[4]), __int_as_float(biB[5]));
    } else {
        // target min, branchless (P=4), 4 slices of 1024, atomic key-min
        b -= SRC_BLKS;
        int pg = b >> 2;
        int sl = b & 3;
        load_packed_slice(s_pk, g_tgt_bc, sl * SLT, SLT, tid);
        __syncthreads();

        int i0 = pg * (RTPB * PT) + tid;
        u64 px[PT], py[PT], pz[PT];
        #pragma unroll
        for (int p = 0; p < PT; p++) {
            float4 q = g_pts[i0 + p * RTPB];
            px[p] = pk2(-q.x, -q.x); py[p] = pk2(-q.y, -q.y); pz[p] = pk2(-q.z, -q.z);
        }

        float m0[PT], m1[PT];
        #pragma unroll
        for (int p = 0; p < PT; p++) { m0[p] = 1e30f; m1[p] = 1e30f; }
        #pragma unroll 4
        for (int t = 0; t < SLT/2; t++) {
            ulonglong2 U = s_pk[2*t], V = s_pk[2*t+1];
            #pragma unroll
            for (int p = 0; p < PT; p++) {
                u64 d = fma2(px[p], U.x, fma2(py[p], U.y, fma2(pz[p], V.x, V.y)));
                float e0, e1; upk2(d, e0, e1);
                m0[p] = fminf(m0[p], e0);
                m1[p] = fminf(m1[p], e1);
            }
        }
        #pragma unroll
        for (int p = 0; p < PT; p++)
            atomicMin(&g_mtei[i0 + p * RTPB], fkey(fminf(m0[p], m1[p])));
    }
}

// ---------------------------------------------------------------------------
// Kernel 3 (fused): global stage-2 + per-point value (blocks 0..255),
// forward loss (blocks 256..287), last block does final reduction.
// ---------------------------------------------------------------------------
__device__ __forceinline__ void merge6(const float* ea, const int* ia,
                                       const float* eb, const int* ib,
                                       float* eo, int* io) {
    int a = 0, b = 0;
    #pragma unroll
    for (int k = 0; k < 6; k++) {
        float va = ea[a], vb = eb[b];
        bool tA = (va <= vb);          // left = earlier slice = lower chunk ids
        eo[k] = tA ? va : vb;
        io[k] = tA ? ia[a] : ib[b];
        a += tA ? 1 : 0;
        b += tA ? 0 : 1;
    }
}

__device__ __forceinline__ void load_list(int s, int i, float* e, int* id) {
    float4 r0 = g_list[s][i][0];
    float4 r1 = g_list[s][i][1];
    float4 r2 = g_list[s][i][2];
    e[0] = r0.x; e[1] = r0.y; e[2] = r0.z; e[3] = r0.w;
    e[4] = r1.x; e[5] = r1.y;
    id[0] = __float_as_int(r1.z); id[1] = __float_as_int(r1.w);
    id[2] = __float_as_int(r2.x); id[3] = __float_as_int(r2.y);
    id[4] = __float_as_int(r2.z); id[5] = __float_as_int(r2.w);
}

__global__ void __launch_bounds__(MRG_TPB) merge_kernel(
        const float* __restrict__ probs, float* __restrict__ out) {
    int tid = threadIdx.x;
    float val;

    if (blockIdx.x < MRG_BLK) {
        int i     = blockIdx.x * MRG_TPB + tid;
        int sface = i >> 3;

        // global top-6 chunk minima across 8 slices
        float me[6]; int mc[6];
        load_list(0, i, me, mc);
        #pragma unroll
        for (int s = 1; s < SLICES; s++) {
            float eb[6], tmp[6]; int ib[6], tmpi[6];
            load_list(s, i, eb, ib);
            merge6(me, mc, eb, ib, tmp, tmpi);
            #pragma unroll
            for (int k = 0; k < 6; k++) { me[k] = tmp[k]; mc[k] = tmpi[k]; }
        }
        // sort selected chunk ids ascending for stable tie-break on rescan
        #pragma unroll
        for (int a = 1; a < 6; a++)
            #pragma unroll
            for (int b2 = a; b2 > 0; b2--)
                if (mc[b2] < mc[b2-1]) { int t = mc[b2]; mc[b2] = mc[b2-1]; mc[b2-1] = t; }

        // global stage-2: rescan the 6 selected chunks (48 candidates)
        float4 p = g_pts[i];
        float pw = p.w;
        float be[6]; int bi[6];
        #pragma unroll
        for (int k = 0; k < 6; k++) { be[k] = 1e30f; bi[k] = -1; }
        #pragma unroll
        for (int k = 0; k < 6; k++) {
            int j0 = mc[k] * CH;
            #pragma unroll
            for (int t = 0; t < CH; t++) {
                float4 q = g_src_bc[j0 + t];
                float e = fmaf(-p.x, q.x, fmaf(-p.y, q.y, fmaf(-p.z, q.z, q.w)));
                try_insert(e, j0 + t, be, bi);
            }
        }

        int selfpos = 6;
        #pragma unroll
        for (int k = 0; k < 6; k++) if (bi[k] == sface) selfpos = k;
        float s5 = 0.0f;
        #pragma unroll
        for (int k = 0; k < 6; k++) {
            bool inc = (k != selfpos) && (k < 5 || selfpos <= 5);
            if (inc) {
                float d = fmaxf(fmaf(2.0f, be[k], pw), 0.0f);
                s5 += probs[bi[k]] * d;
            }
        }
        float mte  = funkey(g_mtei[i]);
        float pp   = probs[sface];
        float mind = fmaxf(fmaf(2.0f, mte, pw), 0.0f);
        val = fmaf(pp, mind, (1.0f - pp) * (s5 * 0.2f));
    } else {
        // forward loss: one face per thread
        int f = (blockIdx.x - MRG_BLK) * MRG_TPB + tid;
        int i = NPTS + f;
        float mte = funkey(g_mtei[i]);
        float d = fmaxf(fmaf(2.0f, mte, g_pts[i].w), 0.0f);
        val = probs[f] * d;
    }

    __shared__ float red[MRG_TPB];
    red[tid] = val;
    __syncthreads();
    #pragma unroll
    for (int s = MRG_TPB/2; s > 0; s >>= 1) {
        if (tid < s) red[tid] += red[tid + s];
        __syncthreads();
    }

    // last-block final reduction (deterministic: one block, fixed order)
    __shared__ bool s_last;
    if (tid == 0) {
        g_partial[blockIdx.x] = red[0];
        __threadfence();
        unsigned done = atomicAdd(&g_mcount, 1u);
        s_last = (done == PART_BLK - 1);
    }
    __syncthreads();
    if (s_last) {
        volatile float* gp = (volatile float*)g_partial;
        float v = gp[tid] + gp[tid + MRG_TPB];            // 0..255
        if (tid < PART_BLK - 2*MRG_TPB) v += gp[tid + 2*MRG_TPB];  // 256..287
        red[tid] = v;
        __syncthreads();
        #pragma unroll
        for (int s = MRG_TPB/2; s > 0; s >>= 1) {
            if (tid < s) red[tid] += red[tid + s];
            __syncthreads();
        }
        if (tid == 0) {
            out[0] = red[0];
            g_mcount = 0;     // reset for next graph replay
        }
    }
}

extern "C" void kernel_launch(void* const* d_in, const int* in_sizes, int n_in,
                              void* d_out, int out_size) {
    const float* sv    = (const float*)d_in[0];
    const int*   sf    = (const int*)  d_in[1];
    const float* tv    = (const float*)d_in[2];
    const int*   tf    = (const int*)  d_in[3];
    const float* probs = (const float*)d_in[4];
    const float* r1u   = (const float*)d_in[5];
    const float* r2u   = (const float*)d_in[6];

    prep_kernel <<<NPTS / TPB, TPB>>>(sv, sf, tv, tf, r1u, r2u);
    rev_kernel  <<<SRC_BLKS + TGT_BLKS, RTPB>>>();          // 1312 blocks
    merge_kernel<<<PART_BLK, MRG_TPB>>>(probs, (float*)d_out);
}

// round 17
// speedup vs baseline: 1.0773x; 1.0753x over previous
#include <cuda_runtime.h>

#define FS 4096
#define FT 4096
#define NV 2048
#define NPTS (FS * 8)            // 32768 sample points
#define NPE  (NPTS + FS)         // + 4096 src barycenters = 36864
#define TPB 256
#define RTPB 128
#define PT 4                     // points per thread (tgt path only)
#define SLICES 8
#define SL 512                   // candidates per slice
#define CH 16                    // chunk size (stage-1 granularity)
#define NCH (SL / CH)            // 32 chunks per slice
#define SRC_PG (NPTS / (RTPB * 2))    // 128 point-groups (256 pts each)
#define TGT_PG (NPE  / (RTPB * PT))   // 72 point-groups (512 pts each)
#define SRC_BLKS (SRC_PG * SLICES)    // 1024
#define TGT_BLKS (TGT_PG * SLICES)    // 576
#define MRG_TPB 128
#define MRG_BLK (NPTS / MRG_TPB)      // 256
#define FSUM_BLK (FS / MRG_TPB)       // 32
#define PART_BLK (MRG_BLK + FSUM_BLK) // 288

typedef unsigned long long u64;

// Scratch (allocation-free: __device__ globals)
__device__ float4 g_src_bc[FS];        // xyz, w = 0.5*|bc|^2 (candidate form)
__device__ float4 g_tgt_bc[FT];        // xyz, w = 0.5*|bc|^2
__device__ float4 g_pts[NPE];          // xyz, w = |p|^2 (full norm)
// packed per-slice record: top-6 chunk-min values + global chunk ids (bitcast)
__device__ float4 g_list[SLICES][NPTS][3];
__device__ unsigned g_mtei[NPE];       // order-preserving float keys, atomicMin
__device__ float  g_partial[PART_BLK];
__device__ unsigned g_mcount;          // zero-initialized; self-resetting

// ---- packed f32x2 helpers (sm_103a) ---------------------------------------
__device__ __forceinline__ u64 pk2(float a, float b) {
    u64 r; asm("mov.b64 %0,{%1,%2};" : "=l"(r) : "f"(a), "f"(b)); return r;
}
__device__ __forceinline__ u64 fma2(u64 a, u64 b, u64 c) {
    u64 d; asm("fma.rn.f32x2 %0,%1,%2,%3;" : "=l"(d) : "l"(a), "l"(b), "l"(c)); return d;
}
__device__ __forceinline__ void upk2(u64 d, float& x, float& y) {
    asm("mov.b64 {%0,%1},%2;" : "=f"(x), "=f"(y) : "l"(d));
}

// order-preserving float <-> uint key (f1 < f2  <=>  key(f1) < key(f2), unsigned)
__device__ __forceinline__ unsigned fkey(float f) {
    unsigned b = __float_as_uint(f);
    return (b & 0x80000000u) ? ~b : (b | 0x80000000u);
}
__device__ __forceinline__ float funkey(unsigned k) {
    return __uint_as_float((k & 0x80000000u) ? (k ^ 0x80000000u) : ~k);
}

// ascending insert, strict < keeps earlier (lower-index) candidate on ties
__device__ __forceinline__ void try_insert(float e, int j, float be[6], int bi[6]) {
    if (e < be[5]) {
        be[5] = e; bi[5] = j;
        #pragma unroll
        for (int k = 5; k > 0; --k) {
            if (be[k] < be[k-1]) {
                float te = be[k]; be[k] = be[k-1]; be[k-1] = te;
                int   ti = bi[k]; bi[k] = bi[k-1]; bi[k-1] = ti;
            }
        }
    }
}

// Pack SL candidates (pair-interleaved) from g[off..off+SL) into smem.
__device__ __forceinline__ void load_packed_slice(ulonglong2* s, const float4* g,
                                                  int off, int tid) {
    for (int t = tid; t < SL/2; t += RTPB) {
        float4 a = g[off + 2*t], b = g[off + 2*t + 1];
        ulonglong2 u0, u1;
        u0.x = pk2(a.x, b.x); u0.y = pk2(a.y, b.y);
        u1.x = pk2(a.z, b.z); u1.y = pk2(a.w, b.w);
        s[2*t]   = u0;
        s[2*t+1] = u1;
    }
}

// ---------------------------------------------------------------------------
// Kernel 1: barycenters + sampled points (vertex arrays staged in smem).
// Also re-initializes g_mtei each call (graph-replay safe: same stream).
// ---------------------------------------------------------------------------
__global__ void __launch_bounds__(TPB) prep_kernel(
        const float* __restrict__ sv, const int* __restrict__ sf,
        const float* __restrict__ tv, const int* __restrict__ tf,
        const float* __restrict__ r1u, const float* __restrict__ r2u) {
    __shared__ float s_v[NV * 6];      // sv then tv, 48 KB
    int tid = threadIdx.x;
    {
        const float4* sv4 = (const float4*)sv;
        const float4* tv4 = (const float4*)tv;
        float4* s4 = (float4*)s_v;
        #pragma unroll
        for (int k = 0; k < (NV*3)/(4*TPB); k++) {
            int idx = tid + k * TPB;
            s4[idx]              = sv4[idx];
            s4[idx + (NV*3)/4]   = tv4[idx];
        }
    }
    __syncthreads();
    const float* s_sv = s_v;
    const float* s_tv = s_v + NV * 3;

    int i = blockIdx.x * TPB + tid;
    g_mtei[i] = 0xFFFFFFFFu;           // +inf key
    if (i < FS) {
        g_mtei[NPTS + i] = 0xFFFFFFFFu;
        int a = sf[3*i+0], b = sf[3*i+1], c = sf[3*i+2];
        float x = (s_sv[3*a+0] + s_sv[3*b+0] + s_sv[3*c+0]) * (1.0f/3.0f);
        float y = (s_sv[3*a+1] + s_sv[3*b+1] + s_sv[3*c+1]) * (1.0f/3.0f);
        float z = (s_sv[3*a+2] + s_sv[3*b+2] + s_sv[3*c+2]) * (1.0f/3.0f);
        float n2 = x*x + y*y + z*z;
        g_src_bc[i]      = make_float4(x, y, z, 0.5f*n2);
        g_pts[NPTS + i]  = make_float4(x, y, z, n2);
        int ta = tf[i], tb = tf[FT + i], tc = tf[2*FT + i];
        float tx = (s_tv[3*ta+0] + s_tv[3*tb+0] + s_tv[3*tc+0]) * (1.0f/3.0f);
        float ty = (s_tv[3*ta+1] + s_tv[3*tb+1] + s_tv[3*tc+1]) * (1.0f/3.0f);
        float tz = (s_tv[3*ta+2] + s_tv[3*tb+2] + s_tv[3*tc+2]) * (1.0f/3.0f);
        g_tgt_bc[i] = make_float4(tx, ty, tz, 0.5f*(tx*tx + ty*ty + tz*tz));
    }
    {
        int f = i >> 3;
        int a = sf[3*f+0], b = sf[3*f+1], c = sf[3*f+2];
        float r1 = sqrtf(r1u[i]);
        float r2 = r2u[i];
        float w1 = 1.0f - r1;
        float w2 = r1 * (1.0f - r2);
        float w3 = r1 * r2;
        float x = w1*s_sv[3*a+0] + w2*s_sv[3*b+0] + w3*s_sv[3*c+0];
        float y = w1*s_sv[3*a+1] + w2*s_sv[3*b+1] + w3*s_sv[3*c+1];
        float z = w1*s_sv[3*a+2] + w2*s_sv[3*b+2] + w3*s_sv[3*c+2];
        g_pts[i] = make_float4(x, y, z, x*x + y*y + z*z);
    }
}

// ---------------------------------------------------------------------------
// Kernel 2 (fused): src stage-1 chunk-minima top-6 (P=2, CH=16) + tgt min
// (P=4, atomic-min accumulation across slices).
// ---------------------------------------------------------------------------
__global__ void __launch_bounds__(RTPB) rev_kernel() {
    __shared__ ulonglong2 s_pk[SL];   // 8 KB
    int tid = threadIdx.x;
    int b   = blockIdx.x;

    if (b < SRC_BLKS) {
        int pg  = b >> 3;
        int sl  = b & 7;
        int jb  = sl * SL;
        load_packed_slice(s_pk, g_src_bc, jb, tid);
        __syncthreads();

        int i0 = pg * 256 + tid;
        int i1 = i0 + 128;
        float4 p0 = g_pts[i0], p1 = g_pts[i1];
        u64 ax = pk2(-p0.x, -p0.x), ay = pk2(-p0.y, -p0.y), az = pk2(-p0.z, -p0.z);
        u64 bx = pk2(-p1.x, -p1.x), by = pk2(-p1.y, -p1.y), bz = pk2(-p1.z, -p1.z);

        // Stage 1: top-6 of chunk minima, ids = GLOBAL chunk id (sl*NCH + c)
        float beA[6], beB[6]; int biA[6], biB[6];
        #pragma unroll
        for (int k = 0; k < 6; k++) {
            beA[k] = 1e30f; biA[k] = -1;
            beB[k] = 1e30f; biB[k] = -1;
        }
        int gc0 = sl * NCH;
        for (int c = 0; c < NCH; c++) {
            float mA = 1e30f, mB = 1e30f;
            int base = CH * c;
            #pragma unroll
            for (int t = 0; t < CH/2; t++) {
                ulonglong2 U = s_pk[base + 2*t], V = s_pk[base + 2*t + 1];
                u64 dA = fma2(ax, U.x, fma2(ay, U.y, fma2(az, V.x, V.y)));
                u64 dB = fma2(bx, U.x, fma2(by, U.y, fma2(bz, V.x, V.y)));
                float e0, e1;
                upk2(dA, e0, e1); mA = fminf(mA, fminf(e0, e1));
                upk2(dB, e0, e1); mB = fminf(mB, fminf(e0, e1));
            }
            try_insert(mA, gc0 + c, beA, biA);
            try_insert(mB, gc0 + c, beB, biB);
        }

        g_list[sl][i0][0] = make_float4(beA[0], beA[1], beA[2], beA[3]);
        g_list[sl][i0][1] = make_float4(beA[4], beA[5],
                                        __int_as_float(biA[0]), __int_as_float(biA[1]));
        g_list[sl][i0][2] = make_float4(__int_as_float(biA[2]), __int_as_float(biA[3]),
                                        __int_as_float(biA[4]), __int_as_float(biA[5]));
        g_list[sl][i1][0] = make_float4(beB[0], beB[1], beB[2], beB[3]);
        g_list[sl][i1][1] = make_float4(beB[4], beB[5],
                                        __int_as_float(biB[0]), __int_as_float(biB[1]));
        g_list[sl][i1][2] = make_float4(__int_as_float(biB[2]), __int_as_float(biB[3]),
                                        __int_as_float(biB[4]), __int_as_float(biB[5]));
    } else {
        // target min, branchless (P=4), accumulated via exact atomic key-min
        b -= SRC_BLKS;
        int pg = b >> 3;
        int sl = b & 7;
        load_packed_slice(s_pk, g_tgt_bc, sl * SL, tid);
        __syncthreads();

        int i0 = pg * (RTPB * PT) + tid;
        u64 px[PT], py[PT], pz[PT];
        #pragma unroll
        for (int p = 0; p < PT; p++) {
            float4 q = g_pts[i0 + p * RTPB];
            px[p] = pk2(-q.x, -q.x); py[p] = pk2(-q.y, -q.y); pz[p] = pk2(-q.z, -q.z);
        }

        float m0[PT], m1[PT];
        #pragma unroll
        for (int p = 0; p < PT; p++) { m0[p] = 1e30f; m1[p] = 1e30f; }
        #pragma unroll 4
        for (int t = 0; t < SL/2; t++) {
            ulonglong2 U = s_pk[2*t], V = s_pk[2*t+1];
            #pragma unroll
            for (int p = 0; p < PT; p++) {
                u64 d = fma2(px[p], U.x, fma2(py[p], U.y, fma2(pz[p], V.x, V.y)));
                float e0, e1; upk2(d, e0, e1);
                m0[p] = fminf(m0[p], e0);
                m1[p] = fminf(m1[p], e1);
            }
        }
        #pragma unroll
        for (int p = 0; p < PT; p++)
            atomicMin(&g_mtei[i0 + p * RTPB], fkey(fminf(m0[p], m1[p])));
    }
}

// ---------------------------------------------------------------------------
// Kernel 3 (fused): global stage-2 + per-point value (blocks 0..255),
// forward loss (blocks 256..287), last block does final reduction.
// ---------------------------------------------------------------------------
__device__ __forceinline__ void merge6(const float* ea, const int* ia,
                                       const float* eb, const int* ib,
                                       float* eo, int* io) {
    int a = 0, b = 0;
    #pragma unroll
    for (int k = 0; k < 6; k++) {
        float va = ea[a], vb = eb[b];
        bool tA = (va <= vb);          // left = earlier slice = lower chunk ids
        eo[k] = tA ? va : vb;
        io[k] = tA ? ia[a] : ib[b];
        a += tA ? 1 : 0;
        b += tA ? 0 : 1;
    }
}

__device__ __forceinline__ void load_list(int s, int i, float* e, int* id) {
    float4 r0 = g_list[s][i][0];
    float4 r1 = g_list[s][i][1];
    float4 r2 = g_list[s][i][2];
    e[0] = r0.x; e[1] = r0.y; e[2] = r0.z; e[3] = r0.w;
    e[4] = r1.x; e[5] = r1.y;
    id[0] = __float_as_int(r1.z); id[1] = __float_as_int(r1.w);
    id[2] = __float_as_int(r2.x); id[3] = __float_as_int(r2.y);
    id[4] = __float_as_int(r2.z); id[5] = __float_as_int(r2.w);
}

__global__ void __launch_bounds__(MRG_TPB) merge_kernel(
        const float* __restrict__ probs, float* __restrict__ out) {
    int tid = threadIdx.x;
    float val;

    if (blockIdx.x < MRG_BLK) {
        int i     = blockIdx.x * MRG_TPB + tid;
        int sface = i >> 3;

        // global top-6 chunk minima across 8 slices
        float me[6]; int mc[6];
        load_list(0, i, me, mc);
        #pragma unroll
        for (int s = 1; s < SLICES; s++) {
            float eb[6], tmp[6]; int ib[6], tmpi[6];
            load_list(s, i, eb, ib);
            merge6(me, mc, eb, ib, tmp, tmpi);
            #pragma unroll
            for (int k = 0; k < 6; k++) { me[k] = tmp[k]; mc[k] = tmpi[k]; }
        }
        // sort selected chunk ids ascending for stable tie-break on rescan
        #pragma unroll
        for (int a = 1; a < 6; a++)
            #pragma unroll
            for (int b2 = a; b2 > 0; b2--)
                if (mc[b2] < mc[b2-1]) { int t = mc[b2]; mc[b2] = mc[b2-1]; mc[b2-1] = t; }

        // global stage-2: rescan the 6 selected chunks (96 candidates)
        float4 p = g_pts[i];
        float pw = p.w;
        float be[6]; int bi[6];
        #pragma unroll
        for (int k = 0; k < 6; k++) { be[k] = 1e30f; bi[k] = -1; }
        #pragma unroll
        for (int k = 0; k < 6; k++) {
            int j0 = mc[k] * CH;
            #pragma unroll
            for (int t = 0; t < CH; t++) {
                float4 q = g_src_bc[j0 + t];
                float e = fmaf(-p.x, q.x, fmaf(-p.y, q.y, fmaf(-p.z, q.z, q.w)));
                try_insert(e, j0 + t, be, bi);
            }
        }

        int selfpos = 6;
        #pragma unroll
        for (int k = 0; k < 6; k++) if (bi[k] == sface) selfpos = k;
        float s5 = 0.0f;
        #pragma unroll
        for (int k = 0; k < 6; k++) {
            bool inc = (k != selfpos) && (k < 5 || selfpos <= 5);
            if (inc) {
                float d = fmaxf(fmaf(2.0f, be[k], pw), 0.0f);
                s5 += probs[bi[k]] * d;
            }
        }
        float mte  = funkey(g_mtei[i]);
        float pp   = probs[sface];
        float mind = fmaxf(fmaf(2.0f, mte, pw), 0.0f);
        val = fmaf(pp, mind, (1.0f - pp) * (s5 * 0.2f));
    } else {
        // forward loss: one face per thread
        int f = (blockIdx.x - MRG_BLK) * MRG_TPB + tid;
        int i = NPTS + f;
        float mte = funkey(g_mtei[i]);
        float d = fmaxf(fmaf(2.0f, mte, g_pts[i].w), 0.0f);
        val = probs[f] * d;
    }

    __shared__ float red[MRG_TPB];
    red[tid] = val;
    __syncthreads();
    #pragma unroll
    for (int s = MRG_TPB/2; s > 0; s >>= 1) {
        if (tid < s) red[tid] += red[tid + s];
        __syncthreads();
    }

    // last-block final reduction (deterministic: one block, fixed order)
    __shared__ bool s_last;
    if (tid == 0) {
        g_partial[blockIdx.x] = red[0];
        __threadfence();
        unsigned done = atomicAdd(&g_mcount, 1u);
        s_last = (done == PART_BLK - 1);
    }
    __syncthreads();
    if (s_last) {
        volatile float* gp = (volatile float*)g_partial;
        float v = gp[tid] + gp[tid + MRG_TPB];            // 0..255
        if (tid < PART_BLK - 2*MRG_TPB) v += gp[tid + 2*MRG_TPB];  // 256..287
        red[tid] = v;
        __syncthreads();
        #pragma unroll
        for (int s = MRG_TPB/2; s > 0; s >>= 1) {
            if (tid < s) red[tid] += red[tid + s];
            __syncthreads();
        }
        if (tid == 0) {
            out[0] = red[0];
            g_mcount = 0;     // reset for next graph replay
        }
    }
}

extern "C" void kernel_launch(void* const* d_in, const int* in_sizes, int n_in,
                              void* d_out, int out_size) {
    const float* sv    = (const float*)d_in[0];
    const int*   sf    = (const int*)  d_in[1];
    const float* tv    = (const float*)d_in[2];
    const int*   tf    = (const int*)  d_in[3];
    const float* probs = (const float*)d_in[4];
    const float* r1u   = (const float*)d_in[5];
    const float* r2u   = (const float*)d_in[6];

    prep_kernel <<<NPTS / TPB, TPB>>>(sv, sf, tv, tf, r1u, r2u);
    rev_kernel  <<<SRC_BLKS + TGT_BLKS, RTPB>>>();          // 1600 blocks
    merge_kernel<<<PART_BLK, MRG_TPB>>>(probs, (float*)d_out);
}